// round 15
// baseline (speedup 1.0000x reference)
#include <cuda_runtime.h>
#include <cuda_fp16.h>
#include <cstdint>

// ---------------- problem constants ----------------
#define IN_C   64
#define IMG_H  256
#define IMG_W  256
#define OUT_C  128
#define OUT_H  254
#define OUT_W  254
#define NPOS   (IMG_H * IMG_W)          // 65536
#define OUT_HW (OUT_H * OUT_W)

// Winograd F(2,3) along width. CTA: 128 oc x 32 pairs (64 cols). grid (4, 254).
#define NUM_TILES 12                     // q(4) x kh(3), tIdx = q*3+kh

// smem layout
#define SM_A         0                   // 2 stages x 16KB (Wq tile 128x64 fp16 SW128)
#define A_STAGE      16384
#define SM_M         32768               // 12 planes x (32 pair-rows x 128B)
#define M_PLANE      4096
#define SM_RAW       81920               // 3 strips x 66 pos-rows x 128B
#define STRIP_STRIDE 8448                // 66*128
#define STRIP_CHUNKS 528                 // 66 x 8 chunks of 16B
#define SMEM_TOTAL   107264              // 32768 + 49152 + 25344

// ---------------- device scratch (no allocs allowed) ----------------
__device__ __align__(1024) __half g_x[NPOS * IN_C + 512];     // NHWC fp16 (+pad)
__device__ __align__(1024) __half g_w2[NUM_TILES * OUT_C * IN_C]; // transformed weights

// ---------------- helpers ----------------
__device__ __forceinline__ uint32_t smem_u32(const void* p) {
    uint32_t a;
    asm("{ .reg .u64 t; cvta.to.shared.u64 t, %1; cvt.u32.u64 %0, t; }" : "=r"(a) : "l"(p));
    return a;
}
__device__ __forceinline__ uint32_t sw128(uint32_t o) { return o ^ ((o >> 3) & 0x70); }
__device__ __forceinline__ void cp_async16(uint32_t dst, const void* src) {
    asm volatile("cp.async.cg.shared.global [%0], [%1], 16;" :: "r"(dst), "l"(src) : "memory");
}
__device__ __forceinline__ void cp_commit() {
    asm volatile("cp.async.commit_group;" ::: "memory");
}
template <int N>
__device__ __forceinline__ void cp_wait() {
    asm volatile("cp.async.wait_group %0;" :: "n"(N) : "memory");
}
__device__ __forceinline__ void ldsm4(uint32_t* r, uint32_t addr) {
    asm volatile("ldmatrix.sync.aligned.m8n8.x4.shared.b16 {%0,%1,%2,%3}, [%4];"
                 : "=r"(r[0]), "=r"(r[1]), "=r"(r[2]), "=r"(r[3]) : "r"(addr));
}
__device__ __forceinline__ void ldsm2(uint32_t* r, uint32_t addr) {
    asm volatile("ldmatrix.sync.aligned.m8n8.x2.shared.b16 {%0,%1}, [%2];"
                 : "=r"(r[0]), "=r"(r[1]) : "r"(addr));
}
__device__ __forceinline__ void mma16816(float* d, const uint32_t* a, uint32_t b0, uint32_t b1) {
    asm volatile("mma.sync.aligned.m16n8k16.row.col.f32.f16.f16.f32 "
                 "{%0,%1,%2,%3}, {%4,%5,%6,%7}, {%8,%9}, {%0,%1,%2,%3};"
                 : "+f"(d[0]), "+f"(d[1]), "+f"(d[2]), "+f"(d[3])
                 : "r"(a[0]), "r"(a[1]), "r"(a[2]), "r"(a[3]), "r"(b0), "r"(b1));
}

// ---------------- fused prep kernel (R14, unchanged) ----------------
__global__ __launch_bounds__(256) void prep(const float* __restrict__ x,
                                            const float* __restrict__ w) {
    const int tid = threadIdx.x;
    if (blockIdx.x < 512) {
        __shared__ float s[IN_C][129];
        const int pos0 = blockIdx.x * 128;
#pragma unroll
        for (int i = 0; i < 8; i++) {
            const int r  = tid + i * 256;
            const int ic = r >> 5;
            const int p4 = (r & 31) * 4;
            float4 f = *reinterpret_cast<const float4*>(x + (size_t)ic * NPOS + pos0 + p4);
            s[ic][p4 + 0] = f.x; s[ic][p4 + 1] = f.y;
            s[ic][p4 + 2] = f.z; s[ic][p4 + 3] = f.w;
        }
        __syncthreads();
#pragma unroll
        for (int i = 0; i < 4; i++) {
            const int c   = tid + i * 256;
            const int pos = c >> 3;
            const int ic0 = (c & 7) * 8;
            uint32_t pk[4];
#pragma unroll
            for (int j = 0; j < 4; j++) {
                __half h0 = __float2half(s[ic0 + 2*j][pos]);
                __half h1 = __float2half(s[ic0 + 2*j + 1][pos]);
                pk[j] = (uint32_t)__half_as_ushort(h0) | ((uint32_t)__half_as_ushort(h1) << 16);
            }
            *reinterpret_cast<uint4*>(g_x + (size_t)(pos0 + pos) * IN_C + ic0) =
                make_uint4(pk[0], pk[1], pk[2], pk[3]);
        }
    } else {
        const int idx = (blockIdx.x - 512) * 256 + tid;    // < 98304
        const int tIdx = idx >> 13;
        const int oc   = (idx >> 6) & 127;
        const int ic   = idx & 63;
        const int q    = tIdx / 3;
        const int kh   = tIdx - q * 3;
        const float* gp = w + (size_t)oc * (IN_C * 9) + (size_t)ic * 9 + kh * 3;
        const float g0 = gp[0], g1 = gp[1], g2 = gp[2];
        float v;
        if      (q == 0) v = g0;
        else if (q == 1) v = 0.5f * (g0 + g1 + g2);
        else if (q == 2) v = 0.5f * (g0 - g1 + g2);
        else             v = g2;
        g_w2[idx] = __float2half(v);
    }
}

// ---------------- main Winograd HMMA conv kernel (2 CTA/SM) ----------------
// grid (4, 254): blockIdx.x = pair-tile (32 pairs = 64 cols), blockIdx.y = row
__global__ __launch_bounds__(256, 2)
void conv_hmma(const float* __restrict__ bias, float* __restrict__ out)
{
    extern __shared__ char smem[];
    const uint32_t sbase = smem_u32(smem);
    const int tid  = threadIdx.x;
    const int lane = tid & 31;
    const int wid  = tid >> 5;
    const int wm   = wid & 1;            // oc 0-63 / 64-127
    const int wn   = wid >> 1;           // 0..3, 8 pairs each
    const int oh   = blockIdx.y;
    const int ow0  = blockIdx.x * 64;    // output col base

    // A ldmatrix lane mapping (validated)
    const int rowA = ((lane >> 3) & 1) * 8 + (lane & 7);
    const int kbA  = (lane >> 4) * 16;
    // B ldmatrix.x2 lane mapping: lanes 0-15 carry addresses (row n, kb half)
    const int rowB2 = lane & 7;
    const int kbB2  = ((lane >> 3) & 1) * 16;

    // y accumulators: [mi][c] c=0,1 pairs for oc row, c=2,3 for +8 row.  transient mq.
    float y0[4][4], y1[4][4], mq[4][4];
#pragma unroll
    for (int a = 0; a < 4; a++)
#pragma unroll
        for (int c = 0; c < 4; c++) { y0[a][c] = 0.0f; y1[a][c] = 0.0f; }

    // ---- issue raw strips (3 kh x 66 pos x 64 ic) + first A tiles ----
    for (int i = tid; i < 3 * STRIP_CHUNKS; i += 256) {
        const int strip = i / STRIP_CHUNKS;
        const int c     = i - strip * STRIP_CHUNKS;
        const int yg    = (oh + strip) * IMG_W + ow0;
        cp_async16(sbase + SM_RAW + strip * STRIP_STRIDE + sw128((uint32_t)c * 16),
                   g_x + (size_t)yg * IN_C + c * 8);
    }
    auto issue_A = [&](int t) {
        const __half* src = g_w2 + (size_t)t * OUT_C * IN_C;
        const uint32_t sb = sbase + SM_A + (t & 1) * A_STAGE;
#pragma unroll
        for (int i = 0; i < 4; i++) {
            const uint32_t chunk = tid + i * 256;          // 0..1023
            cp_async16(sb + sw128(chunk * 16), src + chunk * 8);
        }
    };
    issue_A(0);
    cp_commit();            // g0: strips + A0
    issue_A(1);
    cp_commit();            // g1: A1

    // ---- wait strips+A0, build the 12 m-planes (32 pairs each) ----
    cp_wait<1>();
    __syncthreads();

    for (int i = tid; i < 3 * 32 * 32; i += 256) {         // (kh, pair, ic2)
        const int ic2 = i & 31;
        const int p   = (i >> 5) & 31;
        const int kh  = i >> 10;
        const uint32_t co = (uint32_t)ic2 * 4;
        const char* rb = smem + SM_RAW + kh * STRIP_STRIDE;
        __half2 d0 = *reinterpret_cast<const __half2*>(rb + sw128((2*p + 0) * 128 + co));
        __half2 d1 = *reinterpret_cast<const __half2*>(rb + sw128((2*p + 1) * 128 + co));
        __half2 d2 = *reinterpret_cast<const __half2*>(rb + sw128((2*p + 2) * 128 + co));
        __half2 d3 = *reinterpret_cast<const __half2*>(rb + sw128((2*p + 3) * 128 + co));
        __half2 m0 = __hsub2(d0, d2);
        __half2 m1 = __hadd2(d1, d2);
        __half2 m2 = __hsub2(d2, d1);
        __half2 m3 = __hsub2(d1, d3);
        const uint32_t po = sw128((uint32_t)p * 128 + co);
        char* mb = smem + SM_M + kh * M_PLANE;
        *reinterpret_cast<__half2*>(mb + 0 * 3 * M_PLANE + po) = m0;
        *reinterpret_cast<__half2*>(mb + 1 * 3 * M_PLANE + po) = m1;
        *reinterpret_cast<__half2*>(mb + 2 * 3 * M_PLANE + po) = m2;
        *reinterpret_cast<__half2*>(mb + 3 * 3 * M_PLANE + po) = m3;
    }
    __syncthreads();

    // ---- mainloop: 12 tiles (q-major), K=64 each ----
#pragma unroll 1
    for (int t = 0; t < NUM_TILES; t++) {
        if (t > 0) {
            if (t < NUM_TILES - 1) cp_wait<1>(); else cp_wait<0>();
            __syncthreads();
        }
        const int q = t / 3;
        const int r3 = t - q * 3;
        if (r3 == 0) {
#pragma unroll
            for (int a = 0; a < 4; a++)
#pragma unroll
                for (int c = 0; c < 4; c++) mq[a][c] = 0.0f;
        }

        const uint32_t aBase = sbase + SM_A + (t & 1) * A_STAGE;
        const uint32_t bBase = sbase + SM_M + t * M_PLANE;

#pragma unroll
        for (int kc = 0; kc < 4; kc++) {
            uint32_t a[4][4];
#pragma unroll
            for (int mi = 0; mi < 4; mi++) {
                const uint32_t o = (uint32_t)(wm * 64 + mi * 16 + rowA) * 128 + kc * 32 + kbA;
                ldsm4(a[mi], aBase + sw128(o));
            }
            uint32_t b[2];
            const uint32_t o = (uint32_t)(wn * 8 + rowB2) * 128 + kc * 32 + kbB2;
            ldsm2(b, bBase + sw128(o));
#pragma unroll
            for (int mi = 0; mi < 4; mi++)
                mma16816(mq[mi], a[mi], b[0], b[1]);
        }

        if (r3 == 2) {                   // q complete: fold into y
#pragma unroll
            for (int a = 0; a < 4; a++)
#pragma unroll
                for (int c = 0; c < 4; c++) {
                    const float v = mq[a][c];
                    if (q == 0)      { y0[a][c] += v; }
                    else if (q == 1) { y0[a][c] += v; y1[a][c] += v; }
                    else if (q == 2) { y0[a][c] += v; y1[a][c] -= v; }
                    else             { y1[a][c] -= v; }
                }
        }

        __syncthreads();
        if (t + 2 < NUM_TILES) { issue_A(t + 2); cp_commit(); }
    }

    // ---- epilogue: interleaved float2 stores ----
#pragma unroll
    for (int mi = 0; mi < 4; mi++) {
        const int oc0 = wm * 64 + mi * 16 + (lane >> 2);
        const float b0 = bias[oc0];
        const float b1 = bias[oc0 + 8];
#pragma unroll
        for (int c2 = 0; c2 < 2; c2++) {
            const int pr  = wn * 8 + (lane & 3) * 2 + c2;  // local pair index
            const int col = ow0 + 2 * pr;
            if (col < OUT_W) {
                float2 v0 = make_float2(y0[mi][c2]     + b0, y1[mi][c2]     + b0);
                float2 v1 = make_float2(y0[mi][c2 + 2] + b1, y1[mi][c2 + 2] + b1);
                *reinterpret_cast<float2*>(out + (size_t)oc0 * OUT_HW + oh * OUT_W + col) = v0;
                *reinterpret_cast<float2*>(out + (size_t)(oc0 + 8) * OUT_HW + oh * OUT_W + col) = v1;
            }
        }
    }
}

// ---------------- launch ----------------
extern "C" void kernel_launch(void* const* d_in, const int* in_sizes, int n_in,
                              void* d_out, int out_size)
{
    const float* x    = (const float*)d_in[0];
    const float* w    = (const float*)d_in[1];
    const float* bias = (const float*)d_in[2];
    float* out        = (float*)d_out;

    cudaFuncSetAttribute(conv_hmma, cudaFuncAttributeMaxDynamicSharedMemorySize, SMEM_TOTAL);

    prep<<<512 + 384, 256>>>(x, w);
    conv_hmma<<<dim3(4, OUT_H), 256, SMEM_TOTAL>>>(bias, out);
}

// round 16
// speedup vs baseline: 1.4183x; 1.4183x over previous
#include <cuda_runtime.h>
#include <cuda_fp16.h>
#include <cstdint>

// ---------------- problem constants ----------------
#define IN_C   64
#define IMG_H  256
#define IMG_W  256
#define OUT_C  128
#define OUT_H  254
#define OUT_W  254
#define NPOS   (IMG_H * IMG_W)          // 65536
#define NTAPS  9
#define OUT_HW (OUT_H * OUT_W)

// CTA tile: M=128 (all oc), N=128 (positions), K=64 per tap (R6 config)
#define N_TILE 128

// smem layout (R6)
#define SM_A        0                   // 2 stages x 16KB (w tap tile, 128x64 fp16, SW128)
#define A_STAGE     16384
#define SM_B        32768               // 3 strips (kh) x 136 rows x 128B (NHWC, SW128)
#define STRIP_STRIDE 17408              // 136*128
#define STRIP_CHUNKS 1040               // 130 rows x 8 chunks of 16B
#define SMEM_TOTAL  (32768 + 3 * STRIP_STRIDE)   // 84992

// ---------------- device scratch (no allocs allowed) ----------------
__device__ __align__(1024) __half g_x[NPOS * IN_C + 256];    // NHWC fp16 (+pad)
__device__ __align__(1024) __half g_w[NTAPS * OUT_C * IN_C]; // [tap][oc][ic] fp16

// ---------------- helpers ----------------
__device__ __forceinline__ uint32_t smem_u32(const void* p) {
    uint32_t a;
    asm("{ .reg .u64 t; cvta.to.shared.u64 t, %1; cvt.u32.u64 %0, t; }" : "=r"(a) : "l"(p));
    return a;
}
__device__ __forceinline__ uint32_t sw128(uint32_t o) { return o ^ ((o >> 3) & 0x70); }
__device__ __forceinline__ void cp_async16(uint32_t dst, const void* src) {
    asm volatile("cp.async.cg.shared.global [%0], [%1], 16;" :: "r"(dst), "l"(src) : "memory");
}
__device__ __forceinline__ void cp_commit() {
    asm volatile("cp.async.commit_group;" ::: "memory");
}
template <int N>
__device__ __forceinline__ void cp_wait() {
    asm volatile("cp.async.wait_group %0;" :: "n"(N) : "memory");
}
__device__ __forceinline__ void ldsm4(uint32_t* r, uint32_t addr) {
    asm volatile("ldmatrix.sync.aligned.m8n8.x4.shared.b16 {%0,%1,%2,%3}, [%4];"
                 : "=r"(r[0]), "=r"(r[1]), "=r"(r[2]), "=r"(r[3]) : "r"(addr));
}
__device__ __forceinline__ void mma16816(float* d, const uint32_t* a, uint32_t b0, uint32_t b1) {
    asm volatile("mma.sync.aligned.m16n8k16.row.col.f32.f16.f16.f32 "
                 "{%0,%1,%2,%3}, {%4,%5,%6,%7}, {%8,%9}, {%0,%1,%2,%3};"
                 : "+f"(d[0]), "+f"(d[1]), "+f"(d[2]), "+f"(d[3])
                 : "r"(a[0]), "r"(a[1]), "r"(a[2]), "r"(a[3]), "r"(b0), "r"(b1));
}

// ---------------- fused prep kernel ----------------
// blocks [0,512): CHW fp32 -> NHWC fp16 transpose, 128 pos x 64 ic each.
// blocks [512,800): weight repack w[oc][ic][3][3] -> g_w[tap][oc][ic].
__global__ __launch_bounds__(256) void prep(const float* __restrict__ x,
                                            const float* __restrict__ w) {
    const int tid = threadIdx.x;
    if (blockIdx.x < 512) {
        __shared__ float s[IN_C][129];
        const int pos0 = blockIdx.x * 128;
#pragma unroll
        for (int i = 0; i < 8; i++) {
            const int r  = tid + i * 256;
            const int ic = r >> 5;
            const int p4 = (r & 31) * 4;
            float4 f = *reinterpret_cast<const float4*>(x + (size_t)ic * NPOS + pos0 + p4);
            s[ic][p4 + 0] = f.x; s[ic][p4 + 1] = f.y;
            s[ic][p4 + 2] = f.z; s[ic][p4 + 3] = f.w;
        }
        __syncthreads();
#pragma unroll
        for (int i = 0; i < 4; i++) {
            const int c   = tid + i * 256;
            const int pos = c >> 3;
            const int ic0 = (c & 7) * 8;
            uint32_t pk[4];
#pragma unroll
            for (int j = 0; j < 4; j++) {
                __half h0 = __float2half(s[ic0 + 2*j][pos]);
                __half h1 = __float2half(s[ic0 + 2*j + 1][pos]);
                pk[j] = (uint32_t)__half_as_ushort(h0) | ((uint32_t)__half_as_ushort(h1) << 16);
            }
            *reinterpret_cast<uint4*>(g_x + (size_t)(pos0 + pos) * IN_C + ic0) =
                make_uint4(pk[0], pk[1], pk[2], pk[3]);
        }
    } else {
        const int idx = (blockIdx.x - 512) * 256 + tid;   // < 73728
        const int tap = idx >> 13;
        const int oc  = (idx >> 6) & 127;
        const int ic  = idx & 63;
        g_w[idx] = __float2half(w[((size_t)oc * IN_C + ic) * NTAPS + tap]);
    }
}

// ---------------- main HMMA conv kernel (R6 structure, verbatim) ----------------
// grid (2, 254): blockIdx.x = col tile (128 wide), blockIdx.y = output row
__global__ __launch_bounds__(256, 2)
void conv_hmma(const float* __restrict__ bias, float* __restrict__ out)
{
    extern __shared__ char smem[];
    const uint32_t sbase = smem_u32(smem);
    const int tid  = threadIdx.x;
    const int lane = tid & 31;
    const int wid  = tid >> 5;
    const int wm   = wid & 1;            // oc 0-63 / 64-127
    const int wn   = wid >> 1;           // 0..3, 32 positions each
    const int oh   = blockIdx.y;
    const int ow0  = blockIdx.x * N_TILE;

    // ldmatrix per-lane address components (validated mapping)
    const int rowA = ((lane >> 3) & 1) * 8 + (lane & 7);
    const int kbA  = (lane >> 4) * 16;
    const int rowB = ((lane >> 4) & 1) * 8 + (lane & 7);
    const int kbB  = ((lane >> 3) & 1) * 16;

    float acc[4][4][4];
#pragma unroll
    for (int a = 0; a < 4; a++)
#pragma unroll
        for (int b = 0; b < 4; b++)
#pragma unroll
            for (int c = 0; c < 4; c++) acc[a][b][c] = 0.0f;

    // ---- load the 3 B strips (once per CTA) ----
    auto issue_strips = [&]() {
        for (int i = tid; i < 3 * STRIP_CHUNKS; i += 256) {
            const int strip = i / STRIP_CHUNKS;
            const int c     = i - strip * STRIP_CHUNKS;
            const int y0    = (oh + strip) * IMG_W + ow0;
            cp_async16(sbase + SM_B + strip * STRIP_STRIDE + sw128((uint32_t)c * 16),
                       g_x + (size_t)y0 * IN_C + c * 8);
        }
    };
    // ---- load one weight tap tile into stage s ----
    auto issue_A = [&](int tap, int s) {
        const __half* src = g_w + (size_t)tap * OUT_C * IN_C;
        const uint32_t sb = sbase + SM_A + s * A_STAGE;
#pragma unroll
        for (int i = 0; i < 4; i++) {
            const uint32_t chunk = tid + i * 256;          // 0..1023
            cp_async16(sb + sw128(chunk * 16), src + chunk * 8);
        }
    };

    issue_strips();
    issue_A(0, 0);
    cp_commit();            // g0: strips + A0
    issue_A(1, 1);
    cp_commit();            // g1: A1

#pragma unroll 1
    for (int t = 0; t < NTAPS; t++) {
        if (t < NTAPS - 1) cp_wait<1>(); else cp_wait<0>();
        __syncthreads();

        const int kh = t / 3;
        const int kw = t - kh * 3;
        const uint32_t aBase = sbase + SM_A + (t & 1) * A_STAGE;
        const uint32_t bBase = sbase + SM_B + kh * STRIP_STRIDE;

#pragma unroll
        for (int kc = 0; kc < 4; kc++) {
            uint32_t a[4][4];
#pragma unroll
            for (int mi = 0; mi < 4; mi++) {
                const uint32_t o = (uint32_t)(wm * 64 + mi * 16 + rowA) * 128 + kc * 32 + kbA;
                ldsm4(a[mi], aBase + sw128(o));
            }
#pragma unroll
            for (int nj = 0; nj < 2; nj++) {
                uint32_t b[4];
                const uint32_t brow = (uint32_t)(kw + wn * 32 + nj * 16 + rowB);
                const uint32_t o = brow * 128 + kc * 32 + kbB;
                ldsm4(b, bBase + sw128(o));
#pragma unroll
                for (int mi = 0; mi < 4; mi++) {
                    mma16816(acc[mi][nj * 2],     a[mi], b[0], b[1]);
                    mma16816(acc[mi][nj * 2 + 1], a[mi], b[2], b[3]);
                }
            }
        }
        __syncthreads();
        if (t + 2 < NTAPS) { issue_A(t + 2, t & 1); cp_commit(); }
    }

    // ---- epilogue: direct gmem stores ----
#pragma unroll
    for (int mi = 0; mi < 4; mi++) {
        const int oc0 = wm * 64 + mi * 16 + (lane >> 2);
        const float b0 = bias[oc0];
        const float b1 = bias[oc0 + 8];
#pragma unroll
        for (int ni = 0; ni < 4; ni++) {
            const int owp = ow0 + wn * 32 + ni * 8 + (lane & 3) * 2;
            if (owp < OUT_W) {
                float2 v0 = make_float2(acc[mi][ni][0] + b0, acc[mi][ni][1] + b0);
                float2 v1 = make_float2(acc[mi][ni][2] + b1, acc[mi][ni][3] + b1);
                *reinterpret_cast<float2*>(out + (size_t)oc0 * OUT_HW + oh * OUT_W + owp) = v0;
                *reinterpret_cast<float2*>(out + (size_t)(oc0 + 8) * OUT_HW + oh * OUT_W + owp) = v1;
            }
        }
    }
}

// ---------------- launch ----------------
extern "C" void kernel_launch(void* const* d_in, const int* in_sizes, int n_in,
                              void* d_out, int out_size)
{
    const float* x    = (const float*)d_in[0];
    const float* w    = (const float*)d_in[1];
    const float* bias = (const float*)d_in[2];
    float* out        = (float*)d_out;

    cudaFuncSetAttribute(conv_hmma, cudaFuncAttributeMaxDynamicSharedMemorySize, SMEM_TOTAL);

    prep<<<512 + (NTAPS * OUT_C * IN_C) / 256, 256>>>(x, w);
    conv_hmma<<<dim3(2, OUT_H), 256, SMEM_TOTAL>>>(bias, out);
}